// round 2
// baseline (speedup 1.0000x reference)
#include <cuda_runtime.h>

// ---------------- problem constants (raster grid 1024x1024) ----------------
#define R_  1024
#define C_  1024
#define N_  (R_ * C_)
#define HL_ (R_ * (C_ - 1))          // horizontal link count
#define L_  (HL_ + (R_ - 1) * C_)    // total links = 2,095,104
#define ITERS_ 15

#define K_FLOW_  0.0405f
#define FLOW_EXP_ 1.25f
#define A_OPEN_  1.3455e-09f
#define C_CLOSE_ 7.11e-24f
#define RWG_     9810.0f             // rho_w * g
#define INV_DX_  (1.0f / 100.0f)
#define INV_DX2_ (1.0f / (100.0f * 100.0f))

// ---------------- device scratch (static; no allocations) ----------------
__device__ __align__(16) float g_x [N_];
__device__ __align__(16) float g_r [N_];
__device__ __align__(16) float g_p [N_];
__device__ __align__(16) float g_v [N_];
__device__ __align__(16) float g_s [N_];
__device__ __align__(16) float g_t [N_];
__device__ __align__(16) float g_r0[N_];
__device__ __align__(16) float g_eff[N_];
__device__ __align__(16) float g_grad[L_];

// BiCGSTAB scalar state, per-iteration slots (deterministic indexing)
__device__ double g_rho [ITERS_ + 2];   // rho[0]=1 ; rho[i+1]=dot(r0,r) at start of iter i
__device__ double g_dr0v[ITERS_ + 1];   // [0]=1 ; [i+1]=dot(r0,v) of iter i
__device__ double g_dts [ITERS_ + 1];   // [0]=1 ; [i+1]=dot(t,s)  of iter i
__device__ double g_dtt [ITERS_ + 1];   // [0]=1 ; [i+1]=dot(t,t)  of iter i

#define EPSD 1e-30

// ---------------- reduction helpers (256-thread blocks) ----------------
__device__ __forceinline__ void block_red1(double v, double* dst) {
    #pragma unroll
    for (int o = 16; o > 0; o >>= 1) v += __shfl_down_sync(0xffffffffu, v, o);
    __shared__ double sm1[8];
    int lane = threadIdx.x & 31, w = threadIdx.x >> 5;
    if (lane == 0) sm1[w] = v;
    __syncthreads();
    if (threadIdx.x < 8) {
        v = sm1[threadIdx.x];
        #pragma unroll
        for (int o = 4; o > 0; o >>= 1) v += __shfl_down_sync(0xffu, v, o);
        if (threadIdx.x == 0) atomicAdd(dst, v);
    }
}

__device__ __forceinline__ void block_red2(double a, double b, double* da, double* db) {
    #pragma unroll
    for (int o = 16; o > 0; o >>= 1) {
        a += __shfl_down_sync(0xffffffffu, a, o);
        b += __shfl_down_sync(0xffffffffu, b, o);
    }
    __shared__ double sma[8], smb[8];
    int lane = threadIdx.x & 31, w = threadIdx.x >> 5;
    if (lane == 0) { sma[w] = a; smb[w] = b; }
    __syncthreads();
    if (threadIdx.x < 8) {
        a = sma[threadIdx.x];
        b = smb[threadIdx.x];
        #pragma unroll
        for (int o = 4; o > 0; o >>= 1) {
            a += __shfl_down_sync(0xffu, a, o);
            b += __shfl_down_sync(0xffu, b, o);
        }
        if (threadIdx.x == 0) { atomicAdd(da, a); atomicAdd(db, b); }
    }
}

// ---------------- stencil helpers ----------------
// xb: x with Dirichlet substitution at boundary inflow(-1) nodes. Only border
// coordinates can be Dirichlet (inflow_outflow = +/-1 * boundary mask), so
// interior lanes never touch io/bed.
__device__ __forceinline__ float xbv(const float* __restrict__ x,
                                     const int* __restrict__ io,
                                     const float* __restrict__ bed,
                                     int r, int c) {
    int n = r * C_ + c;
    float xv = __ldg(&x[n]);
    if (r == 0 || r == R_ - 1 || c == 0 || c == C_ - 1) {
        if (__ldg(&io[n]) == -1) xv = RWG_ * __ldg(&bed[n]);
    }
    return xv;
}

__device__ __forceinline__ float matvec_at(const float* __restrict__ x,
                                           const int* __restrict__ io,
                                           const float* __restrict__ bed,
                                           int r, int c) {
    float xc = xbv(x, io, bed, r, c);
    float a = 0.f;
    if (c > 0)      a += xbv(x, io, bed, r, c - 1) - xc;
    if (c < C_ - 1) a += xbv(x, io, bed, r, c + 1) - xc;
    if (r > 0)      a += xbv(x, io, bed, r - 1, c) - xc;
    if (r < R_ - 1) a += xbv(x, io, bed, r + 1, c) - xc;
    return a * INV_DX2_;
}

// ---------------- prologue ----------------
// per-link hydraulic gradient + scalar-slot init
__global__ void k_grad(const float* __restrict__ cs, const float* __restrict__ q,
                       const int* __restrict__ fd) {
    int l = blockIdx.x * blockDim.x + threadIdx.x;
    if (l == 0) {
        g_rho[0] = 1.0; g_dr0v[0] = 1.0; g_dts[0] = 1.0; g_dtt[0] = 1.0;
        #pragma unroll
        for (int i = 1; i <= ITERS_ + 1; i++) g_rho[i] = 0.0;
        #pragma unroll
        for (int i = 1; i <= ITERS_; i++) { g_dr0v[i] = 0.0; g_dts[i] = 0.0; g_dtt[i] = 0.0; }
    }
    if (l < L_) {
        float s = cs[l];
        float g = q[l] / (K_FLOW_ * powf(s, FLOW_EXP_));
        g_grad[l] = g * g * (float)fd[l];
    }
}

// b = div(grad);  r0 = r = b - A(0);  x = p = v = 0;  rho[1] = dot(r0,r0)
__device__ __forceinline__ float xb0v(const int* __restrict__ io,
                                      const float* __restrict__ bed, int r, int c) {
    if (r == 0 || r == R_ - 1 || c == 0 || c == C_ - 1) {
        int n = r * C_ + c;
        if (__ldg(&io[n]) == -1) return RWG_ * __ldg(&bed[n]);
    }
    return 0.f;
}

__global__ void k_init(const int* __restrict__ io, const float* __restrict__ bed) {
    int n = blockIdx.x * blockDim.x + threadIdx.x;
    int r = n >> 10, c = n & (C_ - 1);
    // b[n] = (grad_right + grad_down - grad_left - grad_up) / DX
    float acc = 0.f;
    if (c < C_ - 1) acc += g_grad[r * (C_ - 1) + c];
    if (r < R_ - 1) acc += g_grad[HL_ + n];
    if (c > 0)      acc -= g_grad[r * (C_ - 1) + c - 1];
    if (r > 0)      acc -= g_grad[HL_ + n - C_];
    float b = acc * INV_DX_;
    // A(0): only nonzero near borders
    float xc = xb0v(io, bed, r, c);
    float a = 0.f;
    if (c > 0)      a += xb0v(io, bed, r, c - 1) - xc;
    if (c < C_ - 1) a += xb0v(io, bed, r, c + 1) - xc;
    if (r > 0)      a += xb0v(io, bed, r - 1, c) - xc;
    if (r < R_ - 1) a += xb0v(io, bed, r + 1, c) - xc;
    float r0 = b - a * INV_DX2_;
    g_r0[n] = r0; g_r[n] = r0;
    g_x[n] = 0.f; g_p[n] = 0.f; g_v[n] = 0.f;
    block_red1((double)(r0 * r0), &g_rho[1]);
}

// ---------------- iteration kernels ----------------
// K1: p = r + beta * (p - omega_prev * v)
__global__ void k_upd_p(int it) {
    __shared__ float sh_beta, sh_om;
    if (threadIdx.x == 0) {
        double rho_n   = g_rho[it + 1];
        double rho_p   = g_rho[it];
        double alpha_p = g_rho[it] / (g_dr0v[it] + EPSD);
        double omega_p = g_dts[it] / (g_dtt[it] + EPSD);
        sh_beta = (float)((rho_n / (rho_p + EPSD)) * (alpha_p / (omega_p + EPSD)));
        sh_om   = (float)omega_p;
    }
    __syncthreads();
    float beta = sh_beta, om = sh_om;
    int i = blockIdx.x * blockDim.x + threadIdx.x;   // over N_/4 float4s
    float4 rv = ((const float4*)g_r)[i];
    float4 pv = ((const float4*)g_p)[i];
    float4 vv = ((const float4*)g_v)[i];
    float4 o;
    o.x = rv.x + beta * (pv.x - om * vv.x);
    o.y = rv.y + beta * (pv.y - om * vv.y);
    o.z = rv.z + beta * (pv.z - om * vv.z);
    o.w = rv.w + beta * (pv.w - om * vv.w);
    ((float4*)g_p)[i] = o;
}

// K2: v = A(p), fused dot(r0, v)
__global__ void k_matvec_v(const int* __restrict__ io, const float* __restrict__ bed, int it) {
    int n = blockIdx.x * blockDim.x + threadIdx.x;
    int r = n >> 10, c = n & (C_ - 1);
    float val = matvec_at(g_p, io, bed, r, c);
    g_v[n] = val;
    float pr = g_r0[n] * val;          // f32 product like the reference dot
    block_red1((double)pr, &g_dr0v[it + 1]);
}

// K3: s = r - alpha * v
__global__ void k_upd_s(int it) {
    __shared__ float sh_al;
    if (threadIdx.x == 0)
        sh_al = (float)(g_rho[it + 1] / (g_dr0v[it + 1] + EPSD));
    __syncthreads();
    float al = sh_al;
    int i = blockIdx.x * blockDim.x + threadIdx.x;
    float4 rv = ((const float4*)g_r)[i];
    float4 vv = ((const float4*)g_v)[i];
    float4 o;
    o.x = rv.x - al * vv.x;
    o.y = rv.y - al * vv.y;
    o.z = rv.z - al * vv.z;
    o.w = rv.w - al * vv.w;
    ((float4*)g_s)[i] = o;
}

// K4: t = A(s), fused dot(t,s) and dot(t,t)
__global__ void k_matvec_t(const int* __restrict__ io, const float* __restrict__ bed, int it) {
    int n = blockIdx.x * blockDim.x + threadIdx.x;
    int r = n >> 10, c = n & (C_ - 1);
    float val = matvec_at(g_s, io, bed, r, c);
    g_t[n] = val;
    float sc = g_s[n];
    float pts = val * sc;
    float ptt = val * val;
    block_red2((double)pts, (double)ptt, &g_dts[it + 1], &g_dtt[it + 1]);
}

// K5: x += alpha*p + omega*s ; r = s - omega*t ; fused dot(r0, r_new) -> rho[it+2]
__global__ void k_upd_xr(int it) {
    __shared__ float sh_al, sh_om;
    if (threadIdx.x == 0) {
        sh_al = (float)(g_rho[it + 1] / (g_dr0v[it + 1] + EPSD));
        sh_om = (float)(g_dts[it + 1] / (g_dtt[it + 1] + EPSD));
    }
    __syncthreads();
    float al = sh_al, om = sh_om;
    int i = blockIdx.x * blockDim.x + threadIdx.x;   // over N_/4
    float4 xv  = ((const float4*)g_x )[i];
    float4 pv  = ((const float4*)g_p )[i];
    float4 sv  = ((const float4*)g_s )[i];
    float4 tv  = ((const float4*)g_t )[i];
    float4 r0v = ((const float4*)g_r0)[i];
    float4 xn, rn;
    xn.x = (xv.x + al * pv.x) + om * sv.x;  rn.x = sv.x - om * tv.x;
    xn.y = (xv.y + al * pv.y) + om * sv.y;  rn.y = sv.y - om * tv.y;
    xn.z = (xv.z + al * pv.z) + om * sv.z;  rn.z = sv.z - om * tv.z;
    xn.w = (xv.w + al * pv.w) + om * sv.w;  rn.w = sv.w - om * tv.w;
    ((float4*)g_x)[i] = xn;
    ((float4*)g_r)[i] = rn;
    double d = (double)(r0v.x * rn.x) + (double)(r0v.y * rn.y)
             + (double)(r0v.z * rn.z) + (double)(r0v.w * rn.w);
    block_red1(d, &g_rho[it + 2]);
}

// ---------------- epilogue ----------------
__global__ void k_eff(const float* __restrict__ bed, const float* __restrict__ ob) {
    int n = blockIdx.x * blockDim.x + threadIdx.x;
    float pd = g_x[n] - RWG_ * bed[n];
    float o  = ob[n];
    float wp = fminf(fmaxf(pd, 0.f), o);
    g_eff[n] = o - wp;
}

__global__ void k_out(const float* __restrict__ cs, const float* __restrict__ q,
                      const int* __restrict__ fd,
                      const int* __restrict__ head, const int* __restrict__ tail,
                      float* __restrict__ out, const int* __restrict__ dtp) {
    int l = blockIdx.x * blockDim.x + threadIdx.x;
    if (l >= L_) return;
    float dtf = (float)__ldg(dtp);
    int h = __ldg(&head[l]), t = __ldg(&tail[l]);
    float el = fmaxf(0.5f * (g_eff[h] + g_eff[t]), 1.0f);
    float s = cs[l];
    float melt = A_OPEN_ * q[l] * g_grad[l] * (float)fd[l];
    float closure = C_CLOSE_ * (el * el * el) * s;
    out[l] = fmaxf(s + (melt - closure) * dtf, 0.001f);
}

// ---------------- launch ----------------
extern "C" void kernel_launch(void* const* d_in, const int* in_sizes, int n_in,
                              void* d_out, int out_size) {
    const float* cs   = (const float*)d_in[0];
    const float* q    = (const float*)d_in[1];
    const float* bed  = (const float*)d_in[2];
    const float* ob   = (const float*)d_in[3];
    const int*   fd   = (const int*)  d_in[4];
    const int*   io   = (const int*)  d_in[5];
    const int*   head = (const int*)  d_in[6];
    const int*   tail = (const int*)  d_in[7];
    const int*   dtp  = (const int*)  d_in[8];
    float* out = (float*)d_out;

    const int TB = 256;
    const int GB_L = (L_ + TB - 1) / TB;   // 8184
    const int GB_N = N_ / TB;              // 4096
    const int GB_4 = (N_ / 4) / TB;        // 1024

    k_grad<<<GB_L, TB>>>(cs, q, fd);
    k_init<<<GB_N, TB>>>(io, bed);

    for (int it = 0; it < ITERS_; ++it) {
        k_upd_p  <<<GB_4, TB>>>(it);
        k_matvec_v<<<GB_N, TB>>>(io, bed, it);
        k_upd_s  <<<GB_4, TB>>>(it);
        k_matvec_t<<<GB_N, TB>>>(io, bed, it);
        k_upd_xr <<<GB_4, TB>>>(it);
    }

    k_eff<<<GB_N, TB>>>(bed, ob);
    k_out<<<GB_L, TB>>>(cs, q, fd, head, tail, out, dtp);
}

// round 3
// speedup vs baseline: 1.0408x; 1.0408x over previous
#include <cuda_runtime.h>

// ---------------- problem constants (raster grid 1024x1024) ----------------
#define R_  1024
#define C_  1024
#define N_  (R_ * C_)
#define HL_ (R_ * (C_ - 1))          // horizontal link count
#define L_  (HL_ + (R_ - 1) * C_)    // total links = 2,095,104
#define ITERS_ 15
#define NSLOT 32

#define K_FLOW_  0.0405f
#define FLOW_EXP_ 1.25f
#define A_OPEN_  1.3455e-09f
#define C_CLOSE_ 7.11e-24f
#define RWG_     9810.0f             // rho_w * g
#define INV_DX_  (1.0f / 100.0f)
#define INV_DX2_ (1.0f / (100.0f * 100.0f))

// ---------------- device scratch (static; no allocations) ----------------
__device__ __align__(16) float g_x [N_];
__device__ __align__(16) float g_r [N_];
__device__ __align__(16) float g_p [N_];
__device__ __align__(16) float g_v [N_];
__device__ __align__(16) float g_s [N_];
__device__ __align__(16) float g_t [N_];
__device__ __align__(16) float g_r0[N_];
__device__ __align__(16) float g_grad[L_];

// BiCGSTAB scalar state: 32 contention-spread slots per logical scalar.
// Logical value = sum of the 32 slots (summed deterministically by consumers).
__device__ double g_rho [(ITERS_ + 2) * NSLOT];  // rho[0]=1 ; rho[i+1]=dot(r0,r)
__device__ double g_dr0v[(ITERS_ + 1) * NSLOT];  // [0]=1 ; [i+1]=dot(r0,v)
__device__ double g_dts [(ITERS_ + 1) * NSLOT];  // [0]=1 ; [i+1]=dot(t,s)
__device__ double g_dtt [(ITERS_ + 1) * NSLOT];  // [0]=1 ; [i+1]=dot(t,t)

#define EPSD 1e-30

__device__ __forceinline__ double slotsum(const double* p) {
    double a = 0.0;
    #pragma unroll
    for (int i = 0; i < NSLOT; i++) a += p[i];
    return a;
}

// ---------------- reduction helpers (256-thread blocks) ----------------
__device__ __forceinline__ void block_red1(double v, double* dst) {
    #pragma unroll
    for (int o = 16; o > 0; o >>= 1) v += __shfl_down_sync(0xffffffffu, v, o);
    __shared__ double sm1[8];
    int lane = threadIdx.x & 31, w = threadIdx.x >> 5;
    if (lane == 0) sm1[w] = v;
    __syncthreads();
    if (threadIdx.x < 8) {
        v = sm1[threadIdx.x];
        #pragma unroll
        for (int o = 4; o > 0; o >>= 1) v += __shfl_down_sync(0xffu, v, o);
        if (threadIdx.x == 0) atomicAdd(dst, v);
    }
}

__device__ __forceinline__ void block_red2(double a, double b, double* da, double* db) {
    #pragma unroll
    for (int o = 16; o > 0; o >>= 1) {
        a += __shfl_down_sync(0xffffffffu, a, o);
        b += __shfl_down_sync(0xffffffffu, b, o);
    }
    __shared__ double sma[8], smb[8];
    int lane = threadIdx.x & 31, w = threadIdx.x >> 5;
    if (lane == 0) { sma[w] = a; smb[w] = b; }
    __syncthreads();
    if (threadIdx.x < 8) {
        a = sma[threadIdx.x];
        b = smb[threadIdx.x];
        #pragma unroll
        for (int o = 4; o > 0; o >>= 1) {
            a += __shfl_down_sync(0xffu, a, o);
            b += __shfl_down_sync(0xffu, b, o);
        }
        if (threadIdx.x == 0) { atomicAdd(da, a); atomicAdd(db, b); }
    }
}

// ---------------- stencil helpers ----------------
// xb: x with Dirichlet substitution at boundary inflow(-1) nodes. Only border
// coordinates can be Dirichlet (inflow_outflow = +/-1 * boundary mask).
__device__ __forceinline__ float xbv(const float* __restrict__ x,
                                     const int* __restrict__ io,
                                     const float* __restrict__ bed,
                                     int r, int c) {
    int n = r * C_ + c;
    float xv = __ldg(&x[n]);
    if (r == 0 || r == R_ - 1 || c == 0 || c == C_ - 1) {
        if (__ldg(&io[n]) == -1) xv = RWG_ * __ldg(&bed[n]);
    }
    return xv;
}

__device__ __forceinline__ float matvec_at(const float* __restrict__ x,
                                           const int* __restrict__ io,
                                           const float* __restrict__ bed,
                                           int r, int c) {
    float xc = xbv(x, io, bed, r, c);
    float a = 0.f;
    if (c > 0)      a += xbv(x, io, bed, r, c - 1) - xc;
    if (c < C_ - 1) a += xbv(x, io, bed, r, c + 1) - xc;
    if (r > 0)      a += xbv(x, io, bed, r - 1, c) - xc;
    if (r < R_ - 1) a += xbv(x, io, bed, r + 1, c) - xc;
    return a * INV_DX2_;
}

// interior 5-point stencil, same add order as matvec_at: left, right, up, down
__device__ __forceinline__ float sten(float l, float rt, float u, float d, float c) {
    float a = (l - c);
    a += (rt - c);
    a += (u - c);
    a += (d - c);
    return a * INV_DX2_;
}

// ---------------- prologue ----------------
// per-link hydraulic gradient + scalar-slot init (block 0 zeroes slots)
__global__ void __launch_bounds__(256) k_grad(const float* __restrict__ cs,
                                              const float* __restrict__ q,
                                              const int* __restrict__ fd) {
    int l = blockIdx.x * blockDim.x + threadIdx.x;
    if (blockIdx.x == 0) {
        for (int i = threadIdx.x; i < (ITERS_ + 2) * NSLOT; i += 256)
            g_rho[i] = (i == 0) ? 1.0 : 0.0;
        for (int i = threadIdx.x; i < (ITERS_ + 1) * NSLOT; i += 256) {
            double v = (i == 0) ? 1.0 : 0.0;
            g_dr0v[i] = v; g_dts[i] = v; g_dtt[i] = v;
        }
    }
    if (l < L_) {
        float s = cs[l];
        float g = q[l] / (K_FLOW_ * powf(s, FLOW_EXP_));
        g_grad[l] = g * g * (float)fd[l];
    }
}

// b = div(grad);  r0 = r = b - A(0);  x = p = v = 0;  rho[1] = dot(r0,r0)
__device__ __forceinline__ float xb0v(const int* __restrict__ io,
                                      const float* __restrict__ bed, int r, int c) {
    if (r == 0 || r == R_ - 1 || c == 0 || c == C_ - 1) {
        int n = r * C_ + c;
        if (__ldg(&io[n]) == -1) return RWG_ * __ldg(&bed[n]);
    }
    return 0.f;
}

__device__ __forceinline__ float init_r0_at(const int* __restrict__ io,
                                            const float* __restrict__ bed,
                                            int r, int c) {
    int n = r * C_ + c;
    float acc = 0.f;
    if (c < C_ - 1) acc += g_grad[r * (C_ - 1) + c];
    if (r < R_ - 1) acc += g_grad[HL_ + n];
    if (c > 0)      acc -= g_grad[r * (C_ - 1) + c - 1];
    if (r > 0)      acc -= g_grad[HL_ + n - C_];
    float b = acc * INV_DX_;
    float xc = xb0v(io, bed, r, c);
    float a = 0.f;
    if (c > 0)      a += xb0v(io, bed, r, c - 1) - xc;
    if (c < C_ - 1) a += xb0v(io, bed, r, c + 1) - xc;
    if (r > 0)      a += xb0v(io, bed, r - 1, c) - xc;
    if (r < R_ - 1) a += xb0v(io, bed, r + 1, c) - xc;
    return b - a * INV_DX2_;
}

__global__ void __launch_bounds__(256) k_init(const int* __restrict__ io,
                                              const float* __restrict__ bed) {
    int i4 = blockIdx.x * blockDim.x + threadIdx.x;   // over N_/4
    int n = i4 << 2;
    int r = n >> 10, c0 = n & (C_ - 1);
    float4 r0v;
    r0v.x = init_r0_at(io, bed, r, c0 + 0);
    r0v.y = init_r0_at(io, bed, r, c0 + 1);
    r0v.z = init_r0_at(io, bed, r, c0 + 2);
    r0v.w = init_r0_at(io, bed, r, c0 + 3);
    ((float4*)g_r0)[i4] = r0v;
    ((float4*)g_r )[i4] = r0v;
    float4 z = make_float4(0.f, 0.f, 0.f, 0.f);
    ((float4*)g_x)[i4] = z;
    ((float4*)g_p)[i4] = z;
    ((float4*)g_v)[i4] = z;
    double acc = (double)(r0v.x * r0v.x) + (double)(r0v.y * r0v.y)
               + (double)(r0v.z * r0v.z) + (double)(r0v.w * r0v.w);
    block_red1(acc, &g_rho[1 * NSLOT + (blockIdx.x & (NSLOT - 1))]);
}

// ---------------- iteration kernels ----------------
// K1: p = r + beta * (p - omega_prev * v)
__global__ void __launch_bounds__(256) k_upd_p(int it) {
    __shared__ float sh_beta, sh_om;
    if (threadIdx.x == 0) {
        double rho_n   = slotsum(&g_rho [(it + 1) * NSLOT]);
        double rho_p   = slotsum(&g_rho [ it      * NSLOT]);
        double alpha_p = rho_p / (slotsum(&g_dr0v[it * NSLOT]) + EPSD);
        double omega_p = slotsum(&g_dts[it * NSLOT]) / (slotsum(&g_dtt[it * NSLOT]) + EPSD);
        sh_beta = (float)((rho_n / (rho_p + EPSD)) * (alpha_p / (omega_p + EPSD)));
        sh_om   = (float)omega_p;
    }
    __syncthreads();
    float beta = sh_beta, om = sh_om;
    int i = blockIdx.x * blockDim.x + threadIdx.x;   // over N_/4 float4s
    float4 rv = ((const float4*)g_r)[i];
    float4 pv = ((const float4*)g_p)[i];
    float4 vv = ((const float4*)g_v)[i];
    float4 o;
    o.x = rv.x + beta * (pv.x - om * vv.x);
    o.y = rv.y + beta * (pv.y - om * vv.y);
    o.z = rv.z + beta * (pv.z - om * vv.z);
    o.w = rv.w + beta * (pv.w - om * vv.w);
    ((float4*)g_p)[i] = o;
}

// K2: v = A(p), fused dot(r0, v). float4 fast path for deep-interior points.
__global__ void __launch_bounds__(256) k_matvec_v(const int* __restrict__ io,
                                                  const float* __restrict__ bed, int it) {
    int i4 = blockIdx.x * blockDim.x + threadIdx.x;   // over N_/4
    int n = i4 << 2;
    int r = n >> 10, c0 = n & (C_ - 1);
    const float* __restrict__ x = g_p;
    float4 out;
    if (r >= 2 && r <= R_ - 3 && c0 >= 4 && c0 <= C_ - 8) {
        float4 xc = ((const float4*)x)[i4];
        float4 xu = ((const float4*)x)[i4 - (C_ / 4)];
        float4 xd = ((const float4*)x)[i4 + (C_ / 4)];
        float xl = __ldg(&x[n - 1]);
        float xr = __ldg(&x[n + 4]);
        out.x = sten(xl,   xc.y, xu.x, xd.x, xc.x);
        out.y = sten(xc.x, xc.z, xu.y, xd.y, xc.y);
        out.z = sten(xc.y, xc.w, xu.z, xd.z, xc.z);
        out.w = sten(xc.z, xr,   xu.w, xd.w, xc.w);
    } else {
        out.x = matvec_at(x, io, bed, r, c0 + 0);
        out.y = matvec_at(x, io, bed, r, c0 + 1);
        out.z = matvec_at(x, io, bed, r, c0 + 2);
        out.w = matvec_at(x, io, bed, r, c0 + 3);
    }
    ((float4*)g_v)[i4] = out;
    float4 r0v = ((const float4*)g_r0)[i4];
    double acc = (double)(r0v.x * out.x) + (double)(r0v.y * out.y)
               + (double)(r0v.z * out.z) + (double)(r0v.w * out.w);
    block_red1(acc, &g_dr0v[(it + 1) * NSLOT + (blockIdx.x & (NSLOT - 1))]);
}

// K3: s = r - alpha * v
__global__ void __launch_bounds__(256) k_upd_s(int it) {
    __shared__ float sh_al;
    if (threadIdx.x == 0) {
        double rho_n = slotsum(&g_rho [(it + 1) * NSLOT]);
        sh_al = (float)(rho_n / (slotsum(&g_dr0v[(it + 1) * NSLOT]) + EPSD));
    }
    __syncthreads();
    float al = sh_al;
    int i = blockIdx.x * blockDim.x + threadIdx.x;
    float4 rv = ((const float4*)g_r)[i];
    float4 vv = ((const float4*)g_v)[i];
    float4 o;
    o.x = rv.x - al * vv.x;
    o.y = rv.y - al * vv.y;
    o.z = rv.z - al * vv.z;
    o.w = rv.w - al * vv.w;
    ((float4*)g_s)[i] = o;
}

// K4: t = A(s), fused dot(t,s) and dot(t,t)
__global__ void __launch_bounds__(256) k_matvec_t(const int* __restrict__ io,
                                                  const float* __restrict__ bed, int it) {
    int i4 = blockIdx.x * blockDim.x + threadIdx.x;
    int n = i4 << 2;
    int r = n >> 10, c0 = n & (C_ - 1);
    const float* __restrict__ x = g_s;
    float4 out;
    float4 xc;
    if (r >= 2 && r <= R_ - 3 && c0 >= 4 && c0 <= C_ - 8) {
        xc = ((const float4*)x)[i4];
        float4 xu = ((const float4*)x)[i4 - (C_ / 4)];
        float4 xd = ((const float4*)x)[i4 + (C_ / 4)];
        float xl = __ldg(&x[n - 1]);
        float xr = __ldg(&x[n + 4]);
        out.x = sten(xl,   xc.y, xu.x, xd.x, xc.x);
        out.y = sten(xc.x, xc.z, xu.y, xd.y, xc.y);
        out.z = sten(xc.y, xc.w, xu.z, xd.z, xc.z);
        out.w = sten(xc.z, xr,   xu.w, xd.w, xc.w);
    } else {
        xc = ((const float4*)x)[i4];
        out.x = matvec_at(x, io, bed, r, c0 + 0);
        out.y = matvec_at(x, io, bed, r, c0 + 1);
        out.z = matvec_at(x, io, bed, r, c0 + 2);
        out.w = matvec_at(x, io, bed, r, c0 + 3);
    }
    ((float4*)g_t)[i4] = out;
    double ats = (double)(out.x * xc.x) + (double)(out.y * xc.y)
               + (double)(out.z * xc.z) + (double)(out.w * xc.w);
    double att = (double)(out.x * out.x) + (double)(out.y * out.y)
               + (double)(out.z * out.z) + (double)(out.w * out.w);
    int slot = blockIdx.x & (NSLOT - 1);
    block_red2(ats, att, &g_dts[(it + 1) * NSLOT + slot], &g_dtt[(it + 1) * NSLOT + slot]);
}

// K5: x += alpha*p + omega*s ; r = s - omega*t ; fused dot(r0, r_new)
__global__ void __launch_bounds__(256) k_upd_xr(int it) {
    __shared__ float sh_al, sh_om;
    if (threadIdx.x == 0) {
        double rho_n = slotsum(&g_rho [(it + 1) * NSLOT]);
        sh_al = (float)(rho_n / (slotsum(&g_dr0v[(it + 1) * NSLOT]) + EPSD));
        sh_om = (float)(slotsum(&g_dts[(it + 1) * NSLOT]) /
                        (slotsum(&g_dtt[(it + 1) * NSLOT]) + EPSD));
    }
    __syncthreads();
    float al = sh_al, om = sh_om;
    int i = blockIdx.x * blockDim.x + threadIdx.x;   // over N_/4
    float4 xv  = ((const float4*)g_x )[i];
    float4 pv  = ((const float4*)g_p )[i];
    float4 sv  = ((const float4*)g_s )[i];
    float4 tv  = ((const float4*)g_t )[i];
    float4 r0v = ((const float4*)g_r0)[i];
    float4 xn, rn;
    xn.x = (xv.x + al * pv.x) + om * sv.x;  rn.x = sv.x - om * tv.x;
    xn.y = (xv.y + al * pv.y) + om * sv.y;  rn.y = sv.y - om * tv.y;
    xn.z = (xv.z + al * pv.z) + om * sv.z;  rn.z = sv.z - om * tv.z;
    xn.w = (xv.w + al * pv.w) + om * sv.w;  rn.w = sv.w - om * tv.w;
    ((float4*)g_x)[i] = xn;
    ((float4*)g_r)[i] = rn;
    double d = (double)(r0v.x * rn.x) + (double)(r0v.y * rn.y)
             + (double)(r0v.z * rn.z) + (double)(r0v.w * rn.w);
    block_red1(d, &g_rho[(it + 2) * NSLOT + (blockIdx.x & (NSLOT - 1))]);
}

// ---------------- epilogue (eff computed on the fly, identical expressions) ----
__device__ __forceinline__ float eff_at(const float* __restrict__ bed,
                                        const float* __restrict__ ob, int n) {
    float pd = g_x[n] - RWG_ * __ldg(&bed[n]);
    float o  = __ldg(&ob[n]);
    float wp = fminf(fmaxf(pd, 0.f), o);
    return o - wp;
}

__global__ void __launch_bounds__(256) k_out(const float* __restrict__ cs,
                                             const float* __restrict__ q,
                                             const int* __restrict__ fd,
                                             const int* __restrict__ head,
                                             const int* __restrict__ tail,
                                             float* __restrict__ out,
                                             const int* __restrict__ dtp,
                                             const float* __restrict__ bed,
                                             const float* __restrict__ ob) {
    int l = blockIdx.x * blockDim.x + threadIdx.x;
    if (l >= L_) return;
    float dtf = (float)__ldg(dtp);
    int h = __ldg(&head[l]), t = __ldg(&tail[l]);
    float el = fmaxf(0.5f * (eff_at(bed, ob, h) + eff_at(bed, ob, t)), 1.0f);
    float s = cs[l];
    float melt = A_OPEN_ * q[l] * g_grad[l] * (float)fd[l];
    float closure = C_CLOSE_ * (el * el * el) * s;
    out[l] = fmaxf(s + (melt - closure) * dtf, 0.001f);
}

// ---------------- launch ----------------
extern "C" void kernel_launch(void* const* d_in, const int* in_sizes, int n_in,
                              void* d_out, int out_size) {
    const float* cs   = (const float*)d_in[0];
    const float* q    = (const float*)d_in[1];
    const float* bed  = (const float*)d_in[2];
    const float* ob   = (const float*)d_in[3];
    const int*   fd   = (const int*)  d_in[4];
    const int*   io   = (const int*)  d_in[5];
    const int*   head = (const int*)  d_in[6];
    const int*   tail = (const int*)  d_in[7];
    const int*   dtp  = (const int*)  d_in[8];
    float* out = (float*)d_out;

    const int TB = 256;
    const int GB_L = (L_ + TB - 1) / TB;   // 8184
    const int GB_4 = (N_ / 4) / TB;        // 1024 (all node kernels are float4)

    k_grad<<<GB_L, TB>>>(cs, q, fd);
    k_init<<<GB_4, TB>>>(io, bed);

    for (int it = 0; it < ITERS_; ++it) {
        k_upd_p  <<<GB_4, TB>>>(it);
        k_matvec_v<<<GB_4, TB>>>(io, bed, it);
        k_upd_s  <<<GB_4, TB>>>(it);
        k_matvec_t<<<GB_4, TB>>>(io, bed, it);
        k_upd_xr <<<GB_4, TB>>>(it);
    }

    k_out<<<GB_L, TB>>>(cs, q, fd, head, tail, out, dtp, bed, ob);
}

// round 4
// speedup vs baseline: 1.0739x; 1.0318x over previous
#include <cuda_runtime.h>

// ---------------- problem constants (raster grid 1024x1024) ----------------
#define R_  1024
#define C_  1024
#define N_  (R_ * C_)
#define HL_ (R_ * (C_ - 1))          // horizontal link count
#define L_  (HL_ + (R_ - 1) * C_)    // total links = 2,095,104
#define ITERS_ 15
#define NSLOT 32
#define F4ROW (C_ / 4)               // 256 float4 per row
#define TOT4  (N_ / 4)               // 262144 float4 total
#define HALF4 (TOT4 / 2)             // 131072

#define K_FLOW_  0.0405f
#define FLOW_EXP_ 1.25f
#define A_OPEN_  1.3455e-09f
#define C_CLOSE_ 7.11e-24f
#define RWG_     9810.0f             // rho_w * g
#define INV_DX_  (1.0f / 100.0f)
#define INV_DX2_ (1.0f / (100.0f * 100.0f))

// ---------------- device scratch (static; no allocations) ----------------
__device__ __align__(16) float g_x [N_];
__device__ __align__(16) float g_r [N_];
__device__ __align__(16) float g_p [N_];
__device__ __align__(16) float g_v [N_];
__device__ __align__(16) float g_s [N_];
__device__ __align__(16) float g_t [N_];
__device__ __align__(16) float g_r0[N_];
__device__ __align__(16) float g_grad[L_];

// BiCGSTAB scalar state: 32 contention-spread slots per logical scalar.
__device__ double g_rho [(ITERS_ + 2) * NSLOT];
__device__ double g_dr0v[(ITERS_ + 1) * NSLOT];
__device__ double g_dts [(ITERS_ + 1) * NSLOT];
__device__ double g_dtt [(ITERS_ + 1) * NSLOT];

#define EPSD 1e-30

__device__ __forceinline__ double slotsum(const double* p) {
    double a = 0.0;
    #pragma unroll
    for (int i = 0; i < NSLOT; i++) a += p[i];
    return a;
}

// ---------------- reduction helpers (256-thread blocks) ----------------
__device__ __forceinline__ void block_red1(double v, double* dst) {
    #pragma unroll
    for (int o = 16; o > 0; o >>= 1) v += __shfl_down_sync(0xffffffffu, v, o);
    __shared__ double sm1[8];
    int lane = threadIdx.x & 31, w = threadIdx.x >> 5;
    if (lane == 0) sm1[w] = v;
    __syncthreads();
    if (threadIdx.x < 8) {
        v = sm1[threadIdx.x];
        #pragma unroll
        for (int o = 4; o > 0; o >>= 1) v += __shfl_down_sync(0xffu, v, o);
        if (threadIdx.x == 0) atomicAdd(dst, v);
    }
}

__device__ __forceinline__ void block_red2(double a, double b, double* da, double* db) {
    #pragma unroll
    for (int o = 16; o > 0; o >>= 1) {
        a += __shfl_down_sync(0xffffffffu, a, o);
        b += __shfl_down_sync(0xffffffffu, b, o);
    }
    __shared__ double sma[8], smb[8];
    int lane = threadIdx.x & 31, w = threadIdx.x >> 5;
    if (lane == 0) { sma[w] = a; smb[w] = b; }
    __syncthreads();
    if (threadIdx.x < 8) {
        a = sma[threadIdx.x];
        b = smb[threadIdx.x];
        #pragma unroll
        for (int o = 4; o > 0; o >>= 1) {
            a += __shfl_down_sync(0xffu, a, o);
            b += __shfl_down_sync(0xffu, b, o);
        }
        if (threadIdx.x == 0) { atomicAdd(da, a); atomicAdd(db, b); }
    }
}

// ---------------- stencil helpers ----------------
__device__ __forceinline__ float xbv(const float* __restrict__ x,
                                     const int* __restrict__ io,
                                     const float* __restrict__ bed,
                                     int r, int c) {
    int n = r * C_ + c;
    float xv = __ldg(&x[n]);
    if (r == 0 || r == R_ - 1 || c == 0 || c == C_ - 1) {
        if (__ldg(&io[n]) == -1) xv = RWG_ * __ldg(&bed[n]);
    }
    return xv;
}

__device__ __forceinline__ float matvec_at(const float* __restrict__ x,
                                           const int* __restrict__ io,
                                           const float* __restrict__ bed,
                                           int r, int c) {
    float xc = xbv(x, io, bed, r, c);
    float a = 0.f;
    if (c > 0)      a += xbv(x, io, bed, r, c - 1) - xc;
    if (c < C_ - 1) a += xbv(x, io, bed, r, c + 1) - xc;
    if (r > 0)      a += xbv(x, io, bed, r - 1, c) - xc;
    if (r < R_ - 1) a += xbv(x, io, bed, r + 1, c) - xc;
    return a * INV_DX2_;
}

// interior 5-point stencil, same add order: left, right, up, down
__device__ __forceinline__ float sten(float l, float rt, float u, float d, float c) {
    float a = (l - c);
    a += (rt - c);
    a += (u - c);
    a += (d - c);
    return a * INV_DX2_;
}

// 4-wide interior stencil: out f4 from center/up/down f4 + left/right scalars
__device__ __forceinline__ float4 sten4(float4 xc, float4 xu, float4 xd, float xl, float xr) {
    float4 o;
    o.x = sten(xl,   xc.y, xu.x, xd.x, xc.x);
    o.y = sten(xc.x, xc.z, xu.y, xd.y, xc.y);
    o.z = sten(xc.y, xc.w, xu.z, xd.z, xc.z);
    o.w = sten(xc.z, xr,   xu.w, xd.w, xc.w);
    return o;
}

__device__ __forceinline__ double dot4(float4 a, float4 b) {
    return (double)(a.x * b.x) + (double)(a.y * b.y)
         + (double)(a.z * b.z) + (double)(a.w * b.w);
}

// ---------------- prologue ----------------
__global__ void __launch_bounds__(256) k_grad(const float* __restrict__ cs,
                                              const float* __restrict__ q,
                                              const int* __restrict__ fd) {
    int l = blockIdx.x * blockDim.x + threadIdx.x;
    if (blockIdx.x == 0) {
        for (int i = threadIdx.x; i < (ITERS_ + 2) * NSLOT; i += 256)
            g_rho[i] = (i == 0) ? 1.0 : 0.0;
        for (int i = threadIdx.x; i < (ITERS_ + 1) * NSLOT; i += 256) {
            double v = (i == 0) ? 1.0 : 0.0;
            g_dr0v[i] = v; g_dts[i] = v; g_dtt[i] = v;
        }
    }
    if (l < L_) {
        float s = cs[l];
        float g = q[l] / (K_FLOW_ * powf(s, FLOW_EXP_));
        g_grad[l] = g * g * (float)fd[l];
    }
}

__device__ __forceinline__ float xb0v(const int* __restrict__ io,
                                      const float* __restrict__ bed, int r, int c) {
    if (r == 0 || r == R_ - 1 || c == 0 || c == C_ - 1) {
        int n = r * C_ + c;
        if (__ldg(&io[n]) == -1) return RWG_ * __ldg(&bed[n]);
    }
    return 0.f;
}

__device__ __forceinline__ float init_r0_at(const int* __restrict__ io,
                                            const float* __restrict__ bed,
                                            int r, int c) {
    int n = r * C_ + c;
    float acc = 0.f;
    if (c < C_ - 1) acc += g_grad[r * (C_ - 1) + c];
    if (r < R_ - 1) acc += g_grad[HL_ + n];
    if (c > 0)      acc -= g_grad[r * (C_ - 1) + c - 1];
    if (r > 0)      acc -= g_grad[HL_ + n - C_];
    float b = acc * INV_DX_;
    float xc = xb0v(io, bed, r, c);
    float a = 0.f;
    if (c > 0)      a += xb0v(io, bed, r, c - 1) - xc;
    if (c < C_ - 1) a += xb0v(io, bed, r, c + 1) - xc;
    if (r > 0)      a += xb0v(io, bed, r - 1, c) - xc;
    if (r < R_ - 1) a += xb0v(io, bed, r + 1, c) - xc;
    return b - a * INV_DX2_;
}

__global__ void __launch_bounds__(256) k_init(const int* __restrict__ io,
                                              const float* __restrict__ bed) {
    int i4 = blockIdx.x * blockDim.x + threadIdx.x;   // over TOT4
    int n = i4 << 2;
    int r = n >> 10, c0 = n & (C_ - 1);
    float4 r0v;
    r0v.x = init_r0_at(io, bed, r, c0 + 0);
    r0v.y = init_r0_at(io, bed, r, c0 + 1);
    r0v.z = init_r0_at(io, bed, r, c0 + 2);
    r0v.w = init_r0_at(io, bed, r, c0 + 3);
    ((float4*)g_r0)[i4] = r0v;
    ((float4*)g_r )[i4] = r0v;
    float4 z = make_float4(0.f, 0.f, 0.f, 0.f);
    ((float4*)g_x)[i4] = z;
    ((float4*)g_p)[i4] = z;
    ((float4*)g_v)[i4] = z;
    block_red1(dot4(r0v, r0v), &g_rho[1 * NSLOT + (blockIdx.x & (NSLOT - 1))]);
}

// ---------------- iteration kernels ----------------
// K1: p = r + beta*(p - omega_prev*v)    [2 float4 per thread, 512 blocks]
__global__ void __launch_bounds__(256) k_upd_p(int it) {
    __shared__ float sh_beta, sh_om;
    if (threadIdx.x == 0) {
        double rho_n   = slotsum(&g_rho [(it + 1) * NSLOT]);
        double rho_p   = slotsum(&g_rho [ it      * NSLOT]);
        double alpha_p = rho_p / (slotsum(&g_dr0v[it * NSLOT]) + EPSD);
        double omega_p = slotsum(&g_dts[it * NSLOT]) / (slotsum(&g_dtt[it * NSLOT]) + EPSD);
        sh_beta = (float)((rho_n / (rho_p + EPSD)) * (alpha_p / (omega_p + EPSD)));
        sh_om   = (float)omega_p;
    }
    __syncthreads();
    float beta = sh_beta, om = sh_om;
    int g = blockIdx.x * blockDim.x + threadIdx.x;   // 0..HALF4-1
    #pragma unroll
    for (int k = 0; k < 2; k++) {
        int i = g + k * HALF4;
        float4 rv = ((const float4*)g_r)[i];
        float4 pv = ((const float4*)g_p)[i];
        float4 vv = ((const float4*)g_v)[i];
        float4 o;
        o.x = rv.x + beta * (pv.x - om * vv.x);
        o.y = rv.y + beta * (pv.y - om * vv.y);
        o.z = rv.z + beta * (pv.z - om * vv.z);
        o.w = rv.w + beta * (pv.w - om * vv.w);
        ((float4*)g_p)[i] = o;
    }
}

// K2: v = A(p), fused dot(r0,v). Row-pair: each thread does rows (r, r+1), one f4 col.
__global__ void __launch_bounds__(256) k_matvec_v(const int* __restrict__ io,
                                                  const float* __restrict__ bed, int it) {
    int gid = blockIdx.x * blockDim.x + threadIdx.x;   // 0..N_/8-1
    int cq = gid & (F4ROW - 1);
    int rp = gid >> 8;
    int r  = rp << 1;
    int i40 = r * F4ROW + cq;
    int n0  = i40 << 2;
    const float* __restrict__ x = g_p;
    float4 o0, o1;
    if (rp >= 1 && rp <= (R_ / 2) - 2 && cq >= 1 && cq <= F4ROW - 2) {
        float4 xm = ((const float4*)x)[i40 - F4ROW];
        float4 x0 = ((const float4*)x)[i40];
        float4 x1 = ((const float4*)x)[i40 + F4ROW];
        float4 x2 = ((const float4*)x)[i40 + 2 * F4ROW];
        float l0 = __ldg(&x[n0 - 1]),        rr0 = __ldg(&x[n0 + 4]);
        float l1 = __ldg(&x[n0 + C_ - 1]),   rr1 = __ldg(&x[n0 + C_ + 4]);
        o0 = sten4(x0, xm, x1, l0, rr0);
        o1 = sten4(x1, x0, x2, l1, rr1);
    } else {
        int c0 = cq << 2;
        o0.x = matvec_at(x, io, bed, r, c0 + 0);
        o0.y = matvec_at(x, io, bed, r, c0 + 1);
        o0.z = matvec_at(x, io, bed, r, c0 + 2);
        o0.w = matvec_at(x, io, bed, r, c0 + 3);
        o1.x = matvec_at(x, io, bed, r + 1, c0 + 0);
        o1.y = matvec_at(x, io, bed, r + 1, c0 + 1);
        o1.z = matvec_at(x, io, bed, r + 1, c0 + 2);
        o1.w = matvec_at(x, io, bed, r + 1, c0 + 3);
    }
    ((float4*)g_v)[i40]         = o0;
    ((float4*)g_v)[i40 + F4ROW] = o1;
    float4 r0a = ((const float4*)g_r0)[i40];
    float4 r0b = ((const float4*)g_r0)[i40 + F4ROW];
    block_red1(dot4(r0a, o0) + dot4(r0b, o1),
               &g_dr0v[(it + 1) * NSLOT + (blockIdx.x & (NSLOT - 1))]);
}

// K3 (fused): s = r - alpha*v (recomputed at stencil points), t = A(s),
// store s and t at own points, dot(t,s) and dot(t,t).
__device__ __forceinline__ float4 s4(float4 rv, float4 vv, float al) {
    float4 o;
    o.x = rv.x - al * vv.x;
    o.y = rv.y - al * vv.y;
    o.z = rv.z - al * vv.z;
    o.w = rv.w - al * vv.w;
    return o;
}
__device__ __forceinline__ float s1(int n, float al) {
    return __ldg(&g_r[n]) - al * __ldg(&g_v[n]);
}
__device__ __forceinline__ float sb1(const int* __restrict__ io,
                                     const float* __restrict__ bed,
                                     int r, int c, float al) {
    int n = r * C_ + c;
    float sv = s1(n, al);
    if (r == 0 || r == R_ - 1 || c == 0 || c == C_ - 1) {
        if (__ldg(&io[n]) == -1) sv = RWG_ * __ldg(&bed[n]);
    }
    return sv;
}
__device__ __forceinline__ float t_at(const int* __restrict__ io,
                                      const float* __restrict__ bed,
                                      int r, int c, float al) {
    float xc = sb1(io, bed, r, c, al);
    float a = 0.f;
    if (c > 0)      a += sb1(io, bed, r, c - 1, al) - xc;
    if (c < C_ - 1) a += sb1(io, bed, r, c + 1, al) - xc;
    if (r > 0)      a += sb1(io, bed, r - 1, c, al) - xc;
    if (r < R_ - 1) a += sb1(io, bed, r + 1, c, al) - xc;
    return a * INV_DX2_;
}

__global__ void __launch_bounds__(256) k_matvec_t(const int* __restrict__ io,
                                                  const float* __restrict__ bed, int it) {
    __shared__ float sh_al;
    if (threadIdx.x == 0) {
        double rho_n = slotsum(&g_rho [(it + 1) * NSLOT]);
        sh_al = (float)(rho_n / (slotsum(&g_dr0v[(it + 1) * NSLOT]) + EPSD));
    }
    __syncthreads();
    float al = sh_al;
    int gid = blockIdx.x * blockDim.x + threadIdx.x;   // 0..N_/8-1
    int cq = gid & (F4ROW - 1);
    int rp = gid >> 8;
    int r  = rp << 1;
    int i40 = r * F4ROW + cq;
    int n0  = i40 << 2;
    float4 t0, t1, sv0, sv1;
    if (rp >= 1 && rp <= (R_ / 2) - 2 && cq >= 1 && cq <= F4ROW - 2) {
        float4 sm = s4(((const float4*)g_r)[i40 - F4ROW], ((const float4*)g_v)[i40 - F4ROW], al);
        sv0       = s4(((const float4*)g_r)[i40],         ((const float4*)g_v)[i40],         al);
        sv1       = s4(((const float4*)g_r)[i40 + F4ROW], ((const float4*)g_v)[i40 + F4ROW], al);
        float4 s2v= s4(((const float4*)g_r)[i40 + 2*F4ROW], ((const float4*)g_v)[i40 + 2*F4ROW], al);
        float l0 = s1(n0 - 1, al),      rr0 = s1(n0 + 4, al);
        float l1 = s1(n0 + C_ - 1, al), rr1 = s1(n0 + C_ + 4, al);
        t0 = sten4(sv0, sm,  sv1, l0, rr0);
        t1 = sten4(sv1, sv0, s2v, l1, rr1);
    } else {
        int c0 = cq << 2;
        sv0.x = s1(n0 + 0, al); sv0.y = s1(n0 + 1, al);
        sv0.z = s1(n0 + 2, al); sv0.w = s1(n0 + 3, al);
        sv1.x = s1(n0 + C_ + 0, al); sv1.y = s1(n0 + C_ + 1, al);
        sv1.z = s1(n0 + C_ + 2, al); sv1.w = s1(n0 + C_ + 3, al);
        t0.x = t_at(io, bed, r, c0 + 0, al);
        t0.y = t_at(io, bed, r, c0 + 1, al);
        t0.z = t_at(io, bed, r, c0 + 2, al);
        t0.w = t_at(io, bed, r, c0 + 3, al);
        t1.x = t_at(io, bed, r + 1, c0 + 0, al);
        t1.y = t_at(io, bed, r + 1, c0 + 1, al);
        t1.z = t_at(io, bed, r + 1, c0 + 2, al);
        t1.w = t_at(io, bed, r + 1, c0 + 3, al);
    }
    ((float4*)g_s)[i40]         = sv0;
    ((float4*)g_s)[i40 + F4ROW] = sv1;
    ((float4*)g_t)[i40]         = t0;
    ((float4*)g_t)[i40 + F4ROW] = t1;
    double ats = dot4(t0, sv0) + dot4(t1, sv1);
    double att = dot4(t0, t0) + dot4(t1, t1);
    int slot = blockIdx.x & (NSLOT - 1);
    block_red2(ats, att, &g_dts[(it + 1) * NSLOT + slot], &g_dtt[(it + 1) * NSLOT + slot]);
}

// K4: x += alpha*p + omega*s ; r = s - omega*t ; fused dot(r0, r_new)
__global__ void __launch_bounds__(256) k_upd_xr(int it) {
    __shared__ float sh_al, sh_om;
    if (threadIdx.x == 0) {
        double rho_n = slotsum(&g_rho [(it + 1) * NSLOT]);
        sh_al = (float)(rho_n / (slotsum(&g_dr0v[(it + 1) * NSLOT]) + EPSD));
        sh_om = (float)(slotsum(&g_dts[(it + 1) * NSLOT]) /
                        (slotsum(&g_dtt[(it + 1) * NSLOT]) + EPSD));
    }
    __syncthreads();
    float al = sh_al, om = sh_om;
    int g = blockIdx.x * blockDim.x + threadIdx.x;   // 0..HALF4-1
    double d = 0.0;
    #pragma unroll
    for (int k = 0; k < 2; k++) {
        int i = g + k * HALF4;
        float4 xv  = ((const float4*)g_x )[i];
        float4 pv  = ((const float4*)g_p )[i];
        float4 sv  = ((const float4*)g_s )[i];
        float4 tv  = ((const float4*)g_t )[i];
        float4 r0v = ((const float4*)g_r0)[i];
        float4 xn, rn;
        xn.x = (xv.x + al * pv.x) + om * sv.x;  rn.x = sv.x - om * tv.x;
        xn.y = (xv.y + al * pv.y) + om * sv.y;  rn.y = sv.y - om * tv.y;
        xn.z = (xv.z + al * pv.z) + om * sv.z;  rn.z = sv.z - om * tv.z;
        xn.w = (xv.w + al * pv.w) + om * sv.w;  rn.w = sv.w - om * tv.w;
        ((float4*)g_x)[i] = xn;
        ((float4*)g_r)[i] = rn;
        d += dot4(r0v, rn);
    }
    block_red1(d, &g_rho[(it + 2) * NSLOT + (blockIdx.x & (NSLOT - 1))]);
}

// ---------------- epilogue ----------------
__device__ __forceinline__ float eff_at(const float* __restrict__ bed,
                                        const float* __restrict__ ob, int n) {
    float pd = g_x[n] - RWG_ * __ldg(&bed[n]);
    float o  = __ldg(&ob[n]);
    float wp = fminf(fmaxf(pd, 0.f), o);
    return o - wp;
}

__global__ void __launch_bounds__(256) k_out(const float* __restrict__ cs,
                                             const float* __restrict__ q,
                                             const int* __restrict__ fd,
                                             const int* __restrict__ head,
                                             const int* __restrict__ tail,
                                             float* __restrict__ out,
                                             const int* __restrict__ dtp,
                                             const float* __restrict__ bed,
                                             const float* __restrict__ ob) {
    int l = blockIdx.x * blockDim.x + threadIdx.x;
    if (l >= L_) return;
    float dtf = (float)__ldg(dtp);
    int h = __ldg(&head[l]), t = __ldg(&tail[l]);
    float el = fmaxf(0.5f * (eff_at(bed, ob, h) + eff_at(bed, ob, t)), 1.0f);
    float s = cs[l];
    float melt = A_OPEN_ * q[l] * g_grad[l] * (float)fd[l];
    float closure = C_CLOSE_ * (el * el * el) * s;
    out[l] = fmaxf(s + (melt - closure) * dtf, 0.001f);
}

// ---------------- launch ----------------
extern "C" void kernel_launch(void* const* d_in, const int* in_sizes, int n_in,
                              void* d_out, int out_size) {
    const float* cs   = (const float*)d_in[0];
    const float* q    = (const float*)d_in[1];
    const float* bed  = (const float*)d_in[2];
    const float* ob   = (const float*)d_in[3];
    const int*   fd   = (const int*)  d_in[4];
    const int*   io   = (const int*)  d_in[5];
    const int*   head = (const int*)  d_in[6];
    const int*   tail = (const int*)  d_in[7];
    const int*   dtp  = (const int*)  d_in[8];
    float* out = (float*)d_out;

    const int TB = 256;
    const int GB_L  = (L_ + TB - 1) / TB;   // 8184
    const int GB_4  = TOT4 / TB;            // 1024 (k_init)
    const int GB_P  = HALF4 / TB;           // 512  (pointwise, 2 f4/thread)
    const int GB_MV = (N_ / 8) / TB;        // 512  (row-pair matvec)

    k_grad<<<GB_L, TB>>>(cs, q, fd);
    k_init<<<GB_4, TB>>>(io, bed);

    for (int it = 0; it < ITERS_; ++it) {
        k_upd_p   <<<GB_P,  TB>>>(it);
        k_matvec_v<<<GB_MV, TB>>>(io, bed, it);
        k_matvec_t<<<GB_MV, TB>>>(io, bed, it);
        k_upd_xr  <<<GB_P,  TB>>>(it);
    }

    k_out<<<GB_L, TB>>>(cs, q, fd, head, tail, out, dtp, bed, ob);
}